// round 1
// baseline (speedup 1.0000x reference)
#include <cuda_runtime.h>

// Cost volume s2: B=4, C=32, H=W=256, D=9 residual disparities, 8 groups of 4 ch.
// Exploits: y-offset is 0 -> pure 1D lerp along x; res span (0.8) < 1 px ->
// only 3 row taps per side per channel cover all 9 hypotheses;
// var(a,b,c) = (a^2+b^2+c^2)/3 - ((a+b+c)/3)^2 folded into 2 accumulators.

constexpr int Wd = 256, Hd = 256, Cn = 32, Bn = 4, Dn = 9, Gn = 8, CPG = 4;
constexpr int HW = Wd * Hd;

__global__ __launch_bounds__(256) void cost_volume_kernel(
    const float* __restrict__ fref,
    const float* __restrict__ fls,
    const float* __restrict__ frs,
    const float* __restrict__ dinit,
    float* __restrict__ out)
{
    const int idx = blockIdx.x * 256 + threadIdx.x;   // over B*H*W = 262144
    const int b  = idx >> 16;          // HW = 65536
    const int hw = idx & (HW - 1);
    const int w  = idx & (Wd - 1);

    const float disp = dinit[idx];     // [B,1,H,W] -> flat idx
    const float wf = (float)w;

    const float res[9] = {-0.4f,-0.3f,-0.2f,-0.1f,0.0f,0.1f,0.2f,0.3f,0.4f};

    // Precompute per-d fractional weights and 0/1 tap selectors.
    float fxl[9], fxr[9];
    int n_l = 0, n_r = 0;
    unsigned sell = 0, selr = 0;

    #pragma unroll
    for (int d = 0; d < 9; d++) {          // left x = w + (disp + res[d]), increasing in d
        float t  = disp + res[d];
        float xl = wf + t;
        float fl = floorf(xl);
        int   x0 = (int)fl;
        if (d == 0) n_l = x0;              // minimum over d
        sell |= (unsigned)(x0 - n_l) << d; // guaranteed 0 or 1 (span < 1)
        fxl[d] = xl - fl;
    }
    #pragma unroll
    for (int dd = 0; dd < 9; dd++) {       // right x = w - (disp + res[d]), decreasing in d
        int d = 8 - dd;
        float t  = disp + res[d];
        float xr = wf - t;
        float fl = floorf(xr);
        int   x0 = (int)fl;
        if (dd == 0) n_r = x0;             // minimum over d (at d=8)
        selr |= (unsigned)(x0 - n_r) << d;
        fxr[d] = xr - fl;
    }

    const bool vL0 = (n_l     >= 0) & (n_l     < Wd);
    const bool vL1 = (n_l + 1 >= 0) & (n_l + 1 < Wd);
    const bool vL2 = (n_l + 2 >= 0) & (n_l + 2 < Wd);
    const bool vR0 = (n_r     >= 0) & (n_r     < Wd);
    const bool vR1 = (n_r + 1 >= 0) & (n_r + 1 < Wd);
    const bool vR2 = (n_r + 2 >= 0) & (n_r + 2 < Wd);

    const int rowbase0 = b * Cn * HW + (hw - w);   // channel-0 row start
    float* outp = out + b * (Gn * Dn * HW) + hw;

    const float k2 = 1.0f / 12.0f;   // (1/3 var) * (1/4 group mean)
    const float k1 = 1.0f / 36.0f;   // (1/9) * (1/4)

    for (int g = 0; g < Gn; g++) {
        float a2[9], a1[9];
        #pragma unroll
        for (int d = 0; d < 9; d++) { a2[d] = 0.0f; a1[d] = 0.0f; }

        #pragma unroll
        for (int ci = 0; ci < CPG; ci++) {
            const int rb = rowbase0 + (g * CPG + ci) * HW;
            const float* pl = fls + rb;
            const float* pr = frs + rb;

            const float L0 = vL0 ? __ldg(pl + n_l)     : 0.0f;
            const float L1 = vL1 ? __ldg(pl + n_l + 1) : 0.0f;
            const float L2 = vL2 ? __ldg(pl + n_l + 2) : 0.0f;
            const float R0 = vR0 ? __ldg(pr + n_r)     : 0.0f;
            const float R1 = vR1 ? __ldg(pr + n_r + 1) : 0.0f;
            const float R2 = vR2 ? __ldg(pr + n_r + 2) : 0.0f;
            const float F  = __ldg(fref + rb + w);
            const float F2 = F * F;

            const float dL10 = L1 - L0, dL21 = L2 - L1;
            const float dR10 = R1 - R0, dR21 = R2 - R1;

            #pragma unroll
            for (int d = 0; d < 9; d++) {
                const bool  sl = (sell >> d) & 1u;
                const float La = sl ? L1 : L0;
                const float dL = sl ? dL21 : dL10;
                const float wl = fmaf(fxl[d], dL, La);

                const bool  sr = (selr >> d) & 1u;
                const float Ra = sr ? R1 : R0;
                const float dR = sr ? dR21 : dR10;
                const float wr = fmaf(fxr[d], dR, Ra);

                const float s1 = wl + wr + F;
                const float s2 = fmaf(wl, wl, fmaf(wr, wr, F2));
                a2[d] += s2;
                a1[d] = fmaf(s1, s1, a1[d]);
            }
        }

        #pragma unroll
        for (int d = 0; d < 9; d++)
            outp[(g * Dn + d) * HW] = fmaf(a2[d], k2, -a1[d] * k1);
    }
}

extern "C" void kernel_launch(void* const* d_in, const int* in_sizes, int n_in,
                              void* d_out, int out_size)
{
    const float* fref  = (const float*)d_in[0];
    const float* fls   = (const float*)d_in[1];
    const float* frs   = (const float*)d_in[2];
    const float* dinit = (const float*)d_in[3];
    float* out = (float*)d_out;

    cost_volume_kernel<<<(Bn * HW) / 256, 256>>>(fref, fls, frs, dinit, out);
}

// round 2
// speedup vs baseline: 1.4778x; 1.4778x over previous
#include <cuda_runtime.h>

// Cost volume s2: B=4, C=32, H=W=256, D=9, 8 groups of 4 channels.
// y-offset is 0 -> 1D lerp in x; res span 0.8 < 1 px -> 3 taps/side cover all d.
// Select-free "hat" lerp: wl = L1 + min(t,0)*(L1-L0) + max(t,0)*(L2-L1),
// t = x - (n+1). hp/hm are per-d only (channel-independent).
// Left/right packed into f32x2 lanes (FFMA2). var folded into 2 accumulators.

typedef unsigned long long u64;

constexpr int Wd = 256, Cn = 32, Bn = 4, Dn = 9, Gn = 8, CPG = 4;
constexpr int HW = 256 * 256;

__device__ __forceinline__ u64 pk(float a, float b) {
    u64 r; asm("mov.b64 %0, {%1, %2};" : "=l"(r) : "f"(a), "f"(b)); return r;
}
__device__ __forceinline__ void upk(float& a, float& b, u64 v) {
    asm("mov.b64 {%0, %1}, %2;" : "=f"(a), "=f"(b) : "l"(v));
}
__device__ __forceinline__ u64 ffma2(u64 a, u64 b, u64 c) {
    u64 d; asm("fma.rn.f32x2 %0, %1, %2, %3;" : "=l"(d) : "l"(a), "l"(b), "l"(c));
    return d;
}

__global__ __launch_bounds__(128, 6) void cost_volume_kernel(
    const float* __restrict__ fref,
    const float* __restrict__ fls,
    const float* __restrict__ frs,
    const float* __restrict__ dinit,
    float* __restrict__ out)
{
    const int idx = blockIdx.x * 128 + threadIdx.x;   // B*H*W = 262144
    const int b  = idx >> 16;
    const int hw = idx & (HW - 1);
    const int w  = idx & (Wd - 1);

    const float disp = __ldg(dinit + idx);
    const float wf = (float)w;

    // Left taps at n_l..n_l+2, n_l = floor(x_l[d=0]); x_l increases with d.
    const float xl0 = wf + disp - 0.4f;
    const float fll = floorf(xl0);
    const int   n_l = (int)fll;
    const float tl0 = xl0 - fll - 1.0f;            // t at d=0, in [-1, 0)

    // Right taps at n_r..n_r+2, n_r = floor(x_r[d=8]); x_r decreases with d.
    const float xr0 = wf - disp + 0.4f;            // x_r at d=0 (max)
    const float flr = floorf(xr0 - 0.8f);          // floor of x_r at d=8 (min)
    const int   n_r = (int)flr;
    const float tr0 = xr0 - flr - 1.0f;            // t at d=0, in (0, 1.8)... minus 1

    // Per-d hat weights, packed (left, right).
    u64 hp2[9], hm2[9];
    #pragma unroll
    for (int d = 0; d < 9; d++) {
        const float cd = 0.1f * (float)d;
        const float tl = tl0 + cd;
        const float tr = tr0 - cd;
        hp2[d] = pk(fmaxf(tl, 0.0f), fmaxf(tr, 0.0f));
        hm2[d] = pk(fminf(tl, 0.0f), fminf(tr, 0.0f));
    }

    const bool vL0 = (unsigned)(n_l)     < (unsigned)Wd;
    const bool vL1 = (unsigned)(n_l + 1) < (unsigned)Wd;
    const bool vL2 = (unsigned)(n_l + 2) < (unsigned)Wd;
    const bool vR0 = (unsigned)(n_r)     < (unsigned)Wd;
    const bool vR1 = (unsigned)(n_r + 1) < (unsigned)Wd;
    const bool vR2 = (unsigned)(n_r + 2) < (unsigned)Wd;

    const int rowbase0 = b * Cn * HW + (hw - w);   // channel-0 row start
    float* outp = out + b * (Gn * Dn * HW) + hw;

    const float k2 = 1.0f / 12.0f;   // (1/3 var) * (1/4 group mean)
    const float k1 = 1.0f / 36.0f;   // (1/9) * (1/4)

    #pragma unroll 1
    for (int g = 0; g < Gn; g++) {
        u64 P1[CPG], D10[CPG], D21[CPG];
        float Fv[CPG];
        float sF2 = 0.0f;

        #pragma unroll
        for (int ci = 0; ci < CPG; ci++) {
            const int rb = rowbase0 + (g * CPG + ci) * HW;
            const float* pl = fls + rb;
            const float* pr = frs + rb;

            const float L0 = vL0 ? __ldg(pl + n_l)     : 0.0f;
            const float L1 = vL1 ? __ldg(pl + n_l + 1) : 0.0f;
            const float L2 = vL2 ? __ldg(pl + n_l + 2) : 0.0f;
            const float R0 = vR0 ? __ldg(pr + n_r)     : 0.0f;
            const float R1 = vR1 ? __ldg(pr + n_r + 1) : 0.0f;
            const float R2 = vR2 ? __ldg(pr + n_r + 2) : 0.0f;
            const float F  = __ldg(fref + rb + w);

            P1[ci]  = pk(L1, R1);
            D10[ci] = pk(L1 - L0, R1 - R0);
            D21[ci] = pk(L2 - L1, R2 - R1);
            Fv[ci]  = F;
            sF2 = fmaf(F, F, sF2);
        }

        const float bq = k2 * sF2;

        #pragma unroll
        for (int d = 0; d < 9; d++) {
            float acc1 = 0.0f;
            u64   acc2 = 0ull;                      // packed (0.0f, 0.0f)
            #pragma unroll
            for (int ci = 0; ci < CPG; ci++) {
                const u64 lw = ffma2(hp2[d], D21[ci],
                               ffma2(hm2[d], D10[ci], P1[ci]));
                acc2 = ffma2(lw, lw, acc2);
                float wl, wr; upk(wl, wr, lw);
                const float s1 = (wl + wr) + Fv[ci];
                acc1 = fmaf(s1, s1, acc1);
            }
            float a2l, a2r; upk(a2l, a2r, acc2);
            outp[(g * Dn + d) * HW] = fmaf(-k1, acc1, fmaf(k2, a2l + a2r, bq));
        }
    }
}

extern "C" void kernel_launch(void* const* d_in, const int* in_sizes, int n_in,
                              void* d_out, int out_size)
{
    const float* fref  = (const float*)d_in[0];
    const float* fls   = (const float*)d_in[1];
    const float* frs   = (const float*)d_in[2];
    const float* dinit = (const float*)d_in[3];
    float* out = (float*)d_out;

    cost_volume_kernel<<<(Bn * HW) / 128, 128>>>(fref, fls, frs, dinit, out);
}